// round 16
// baseline (speedup 1.0000x reference)
#include <cuda_runtime.h>

#define NN 100000
#define EE 1600000
#define EP (EE + NN)
#define NBLK ((NN + 1023) / 1024)   // 98
#define NEG 0.2f

// ---------------- scratch (static device globals; no allocation) ----------------
__device__ int    g_deg[NN];
__device__ int    g_cursor[NN];
__device__ int    g_offsets[NN + 1];
__device__ int    g_partials[NBLK + 2];
__device__ int    g_csrc[EP];                  // CSR: source node per slot
__device__ int    g_ceid[EP];                  // CSR: original edge id per slot
__device__ float  g_ale1[(size_t)EE * 4];      // per-original-edge layer-1 scores
__device__ float  g_ale2[EE];                  // per-original-edge layer-2 scores
__device__ float4 g_cal1[EP];                  // CSR-ordered layer-1 scores (real edges)
__device__ float  g_cal2[EP];                  // CSR-ordered layer-2 scores (real edges)
__device__ float  g_alpha2[EP];                // CSR-ordered layer-2 numerators
__device__ float  g_h1[(size_t)NN * 128];
__device__ float  g_als1[NN * 4];
__device__ float  g_ald1[NN * 4];
__device__ float  g_h1o[(size_t)NN * 128];
__device__ float  g_h2l[(size_t)NN * 32];
__device__ float  g_als2[NN];
__device__ float  g_ald2[NN];
__device__ float  g_v1[64];                    // folded W1e*a1e: [16 ed][4 h]
__device__ float  g_v2[16];                    // folded W2e*a2e

__device__ __forceinline__ float lrelu(float x) { return x > 0.f ? x : NEG * x; }
__device__ __forceinline__ float elu(float x)   { return x > 0.f ? x : expm1f(x); }

// packed f32x2 helpers (Blackwell; PTX-only form)
__device__ __forceinline__ unsigned long long pack2(float lo, float hi) {
    unsigned long long r;
    asm("mov.b64 %0, {%1, %2};" : "=l"(r) : "r"(__float_as_uint(lo)), "r"(__float_as_uint(hi)));
    return r;
}
__device__ __forceinline__ void unpack2(unsigned long long v, float& lo, float& hi) {
    unsigned int a, b;
    asm("mov.b64 {%0, %1}, %2;" : "=r"(a), "=r"(b) : "l"(v));
    lo = __uint_as_float(a); hi = __uint_as_float(b);
}
__device__ __forceinline__ void ffma2(unsigned long long& d, unsigned long long a, unsigned long long b) {
    asm("fma.rn.f32x2 %0, %1, %2, %3;" : "=l"(d) : "l"(a), "l"(b), "l"(d));
}

// ---------------- init ----------------
__global__ void kz() {
    int i = blockIdx.x * blockDim.x + threadIdx.x;
    if (i < NN) { g_deg[i] = 0; g_cursor[i] = 0; }
}

// fold W_e with a_edge
__global__ void k_prep(const float* __restrict__ W1e, const float* __restrict__ a1e,
                       const float* __restrict__ W2e, const float* __restrict__ a2e) {
    int t = threadIdx.x;
    if (t < 64) {
        int ed = t >> 2, h = t & 3;
        float s = 0.f;
        for (int c = 0; c < 32; c++) s += W1e[ed * 128 + h * 32 + c] * a1e[h * 32 + c];
        g_v1[t] = s;
    } else if (t < 80) {
        int ed = t - 64;
        float s = 0.f;
        for (int c = 0; c < 32; c++) s += W2e[ed * 32 + c] * a2e[c];
        g_v2[ed] = s;
    }
}

// ---------------- per-edge folded scores + degree; 2 edges/thread for MLP ----------------
__global__ void k_edge(const int* __restrict__ ei, const float* __restrict__ ea) {
    __shared__ float v1[64], v2[16];
    int t = threadIdx.x;
    if (t < 64) v1[t] = g_v1[t];
    if (t < 16) v2[t] = g_v2[t];
    __syncthreads();
    int base = blockIdx.x * 512 + t;           // EE = 3125 * 512 exactly
    #pragma unroll
    for (int half = 0; half < 2; half++) {
        int e = base + half * 256;
        int d = ei[EE + e];
        atomicAdd(&g_deg[d], 1);
        float a[16];
        const float4* ep = (const float4*)(ea + (size_t)e * 16);
        float4 q0 = ep[0], q1 = ep[1], q2 = ep[2], q3 = ep[3];
        a[0]=q0.x;a[1]=q0.y;a[2]=q0.z;a[3]=q0.w; a[4]=q1.x;a[5]=q1.y;a[6]=q1.z;a[7]=q1.w;
        a[8]=q2.x;a[9]=q2.y;a[10]=q2.z;a[11]=q2.w; a[12]=q3.x;a[13]=q3.y;a[14]=q3.z;a[15]=q3.w;
        float s0=0,s1=0,s2=0,s3=0,u=0;
        #pragma unroll
        for (int k = 0; k < 16; k++) {
            float x = a[k];
            s0 += x * v1[k*4+0]; s1 += x * v1[k*4+1];
            s2 += x * v1[k*4+2]; s3 += x * v1[k*4+3];
            u  += x * v2[k];
        }
        size_t e4 = (size_t)e * 4;
        g_ale1[e4+0]=s0; g_ale1[e4+1]=s1; g_ale1[e4+2]=s2; g_ale1[e4+3]=s3;
        g_ale2[e] = u;
    }
}

// ---------------- 3-kernel exclusive scan of counts = deg+1 ----------------
__global__ void k_scan1() {
    __shared__ int sh[1024];
    int tid = threadIdx.x;
    int i = blockIdx.x * 1024 + tid;
    int v = (i < NN) ? (g_deg[i] + 1) : 0;
    sh[tid] = v;
    __syncthreads();
    for (int off = 1; off < 1024; off <<= 1) {
        int t = 0;
        if (tid >= off) t = sh[tid - off];
        __syncthreads();
        sh[tid] += t;
        __syncthreads();
    }
    if (i < NN) g_offsets[i] = sh[tid] - v;
    if (tid == 1023) g_partials[blockIdx.x] = sh[1023];
}
__global__ void k_scan2() {
    int run = 0;
    for (int b = 0; b < NBLK; b++) { int t = g_partials[b]; g_partials[b] = run; run += t; }
    g_partials[NBLK] = run;
}
__global__ void k_scan3() {
    int i = blockIdx.x * blockDim.x + threadIdx.x;
    if (i > NN) return;
    if (i == NN) g_offsets[NN] = g_partials[NBLK];
    else g_offsets[i] += g_partials[i >> 10];
}

// ---------------- CSR scatter: src + eid + CSR-ordered scores ----------------
__global__ void k_scatter(const int* __restrict__ ei) {
    int t = blockIdx.x * blockDim.x + threadIdx.x;
    if (t >= EP) return;
    int s, d;
    if (t < EE) { s = ei[t]; d = ei[EE + t]; }
    else        { s = t - EE; d = s; }
    int pos = g_offsets[d] + atomicAdd(&g_cursor[d], 1);
    g_csrc[pos] = s;
    g_ceid[pos] = t;
    if (t < EE) {
        g_cal1[pos] = *(const float4*)&g_ale1[(size_t)t * 4];
        g_cal2[pos] = g_ale2[t];
    }
}

// ---------------- GEMM1 (f32x2 packed) + fused att1 dots ----------------
__global__ void k_gemm1t(const float* __restrict__ X, const float* __restrict__ W,
                         const float* __restrict__ a1s, const float* __restrict__ a1d) {
    __shared__ float xsT[128 * 36];          // [k][row], pad 36
    int tid = threadIdx.x;
    int rowbase = blockIdx.x * 32;
    #pragma unroll 4
    for (int r = 0; r < 32; r++)
        xsT[tid * 36 + r] = X[(size_t)(rowbase + r) * 128 + tid];
    __syncthreads();
    unsigned long long acc2[16];
    #pragma unroll
    for (int p = 0; p < 16; p++) acc2[p] = 0ull;
    for (int k = 0; k < 128; k++) {
        float wk = W[k * 128 + tid];
        unsigned long long wk2 = pack2(wk, wk);
        const double2* xp = (const double2*)&xsT[k * 36];
        #pragma unroll
        for (int rr = 0; rr < 4; rr++) {
            double2 xv = xp[rr];
            ffma2(acc2[rr*4+0], __double_as_longlong(xv.x), wk2);
            ffma2(acc2[rr*4+1], __double_as_longlong(xv.y), wk2);
            double2 xw = xp[rr + 4];
            ffma2(acc2[rr*4+2], __double_as_longlong(xw.x), wk2);
            ffma2(acc2[rr*4+3], __double_as_longlong(xw.y), wk2);
        }
    }
    float as = a1s[tid], ad = a1d[tid];
    int lane = tid & 31, h = tid >> 5;
    #pragma unroll
    for (int rr = 0; rr < 4; rr++) {
        #pragma unroll
        for (int q = 0; q < 4; q++) {
            int r0 = (q >> 1) * 16 + rr * 4 + (q & 1) * 2;
            float lo, hi; unpack2(acc2[rr*4+q], lo, hi);
            g_h1[(size_t)(rowbase + r0) * 128 + tid] = lo;
            g_h1[(size_t)(rowbase + r0 + 1) * 128 + tid] = hi;
            float sl = lo * as, dl = lo * ad, sh = hi * as, dh = hi * ad;
            #pragma unroll
            for (int o = 16; o; o >>= 1) {
                sl += __shfl_xor_sync(~0u, sl, o);
                dl += __shfl_xor_sync(~0u, dl, o);
                sh += __shfl_xor_sync(~0u, sh, o);
                dh += __shfl_xor_sync(~0u, dh, o);
            }
            if (lane == 0) {
                g_als1[(rowbase + r0) * 4 + h] = sl;
                g_ald1[(rowbase + r0) * 4 + h] = dl;
                g_als1[(rowbase + r0 + 1) * 4 + h] = sh;
                g_ald1[(rowbase + r0 + 1) * 4 + h] = dh;
            }
        }
    }
}

// ---------------- layer-1 fused aggregation: warp per node, smem chunk staging ----------------
// A: self-loop score = mean of edge scores (registers)
// B+C merged: per 32-slot chunk, lane computes numerator p for ONE slot (reads csrc/als1/cal1
//             once), stages {p, src} in smem; warp then serially gathers h1 for the chunk.
//             z accumulated alongside; normalization applied once at the end.
__global__ void k_agg1f(const float* __restrict__ b1) {
    __shared__ float4 sp[8][32];
    __shared__ int    ssrc[8][32];
    int wib = threadIdx.x >> 5;
    int wid = (blockIdx.x * blockDim.x + threadIdx.x) >> 5;
    int lane = threadIdx.x & 31;
    if (wid >= NN) return;
    int st = g_offsets[wid], en = g_offsets[wid + 1];
    // pass A
    float s0 = 0.f, s1 = 0.f, s2 = 0.f, s3 = 0.f;
    int selfpos = -1;
    for (int i = st + lane; i < en; i += 32) {
        if (g_ceid[i] < EE) {
            float4 a = g_cal1[i];
            s0 += a.x; s1 += a.y; s2 += a.z; s3 += a.w;
        } else selfpos = i;
    }
    #pragma unroll
    for (int o = 16; o; o >>= 1) {
        s0 += __shfl_xor_sync(~0u, s0, o);
        s1 += __shfl_xor_sync(~0u, s1, o);
        s2 += __shfl_xor_sync(~0u, s2, o);
        s3 += __shfl_xor_sync(~0u, s3, o);
        selfpos = max(selfpos, __shfl_xor_sync(~0u, selfpos, o));
    }
    float inv = 1.f / fmaxf((float)(en - st - 1), 1.f);
    float4 selfsc = make_float4(s0 * inv, s1 * inv, s2 * inv, s3 * inv);
    // merged B+C
    float4 ald = *(const float4*)&g_ald1[wid * 4];
    int h = lane >> 3;
    float z0 = 0.f, z1 = 0.f, z2 = 0.f, z3 = 0.f;
    float4 acc = make_float4(0.f, 0.f, 0.f, 0.f);
    for (int base = st; base < en; base += 32) {
        int i = base + lane;
        float4 p = make_float4(0.f, 0.f, 0.f, 0.f);
        int s = 0;
        if (i < en) {
            s = g_csrc[i];
            float4 als = *(const float4*)&g_als1[s * 4];
            float4 ae = (i == selfpos) ? selfsc : g_cal1[i];
            p.x = __expf(lrelu(als.x + ald.x + ae.x));
            p.y = __expf(lrelu(als.y + ald.y + ae.y));
            p.z = __expf(lrelu(als.z + ald.z + ae.z));
            p.w = __expf(lrelu(als.w + ald.w + ae.w));
            z0 += p.x; z1 += p.y; z2 += p.z; z3 += p.w;
        }
        sp[wib][lane] = p;
        ssrc[wib][lane] = s;
        __syncwarp();
        int cnt = min(32, en - base);
        for (int j = 0; j < cnt; j++) {
            int sj = ssrc[wib][j];
            float a = ((const float*)&sp[wib][j])[h];
            float4 hv = *(const float4*)&g_h1[(size_t)sj * 128 + lane * 4];
            acc.x += a * hv.x; acc.y += a * hv.y;
            acc.z += a * hv.z; acc.w += a * hv.w;
        }
        __syncwarp();
    }
    #pragma unroll
    for (int o = 16; o; o >>= 1) {
        z0 += __shfl_xor_sync(~0u, z0, o);
        z1 += __shfl_xor_sync(~0u, z1, o);
        z2 += __shfl_xor_sync(~0u, z2, o);
        z3 += __shfl_xor_sync(~0u, z3, o);
    }
    float zh = (h == 0) ? z0 : (h == 1) ? z1 : (h == 2) ? z2 : z3;
    float invz = 1.f / zh;
    int j = lane * 4;
    float4 o;
    o.x = elu(acc.x * invz + b1[j+0]); o.y = elu(acc.y * invz + b1[j+1]);
    o.z = elu(acc.z * invz + b1[j+2]); o.w = elu(acc.w * invz + b1[j+3]);
    *(float4*)&g_h1o[(size_t)wid * 128 + j] = o;
}

// ---------------- GEMM2 (f32x2 packed) + fused att2 dots ----------------
__global__ void k_gemm2t(const float* __restrict__ W2,
                         const float* __restrict__ a2s, const float* __restrict__ a2d) {
    __shared__ float xsT[128 * 36];
    int tid = threadIdx.x;
    int c = tid & 31, g = tid >> 5;
    int rowbase = blockIdx.x * 32;
    for (int i = tid; i < 32 * 128; i += 128) {
        int r = i >> 7, k = i & 127;
        xsT[k * 36 + r] = g_h1o[(size_t)(rowbase + r) * 128 + k];
    }
    __syncthreads();
    unsigned long long acc2[4];
    #pragma unroll
    for (int p = 0; p < 4; p++) acc2[p] = 0ull;
    for (int k = 0; k < 128; k++) {
        float wk = W2[k * 32 + c];
        unsigned long long wk2 = pack2(wk, wk);
        const double2* xp = (const double2*)&xsT[k * 36 + g * 8];
        double2 x0 = xp[0], x1 = xp[1];
        ffma2(acc2[0], __double_as_longlong(x0.x), wk2);
        ffma2(acc2[1], __double_as_longlong(x0.y), wk2);
        ffma2(acc2[2], __double_as_longlong(x1.x), wk2);
        ffma2(acc2[3], __double_as_longlong(x1.y), wk2);
    }
    float as = a2s[c], ad = a2d[c];
    #pragma unroll
    for (int p = 0; p < 4; p++) {
        float lo, hi; unpack2(acc2[p], lo, hi);
        int r0 = rowbase + g * 8 + p * 2;
        g_h2l[(size_t)r0 * 32 + c] = lo;
        g_h2l[(size_t)(r0 + 1) * 32 + c] = hi;
        float sl = lo * as, dl = lo * ad, sh = hi * as, dh = hi * ad;
        #pragma unroll
        for (int o = 16; o; o >>= 1) {
            sl += __shfl_xor_sync(~0u, sl, o);
            dl += __shfl_xor_sync(~0u, dl, o);
            sh += __shfl_xor_sync(~0u, sh, o);
            dh += __shfl_xor_sync(~0u, dh, o);
        }
        if (c == 0) {
            g_als2[r0] = sl; g_ald2[r0] = dl;
            g_als2[r0 + 1] = sh; g_ald2[r0 + 1] = dh;
        }
    }
}

// ---------------- layer-2 fused aggregation: warp per node (+ alpha output) ----------------
__global__ void k_agg2f(const float* __restrict__ b2, float* __restrict__ outH2,
                        float* __restrict__ outAlpha) {
    __shared__ float sp[8][32];
    __shared__ int   ssrc[8][32];
    int wib = threadIdx.x >> 5;
    int wid = (blockIdx.x * blockDim.x + threadIdx.x) >> 5;
    int lane = threadIdx.x & 31;
    if (wid >= NN) return;
    int st = g_offsets[wid], en = g_offsets[wid + 1];
    // pass A
    float u = 0.f;
    int selfpos = -1;
    for (int i = st + lane; i < en; i += 32) {
        if (g_ceid[i] < EE) u += g_cal2[i];
        else selfpos = i;
    }
    #pragma unroll
    for (int o = 16; o; o >>= 1) {
        u += __shfl_xor_sync(~0u, u, o);
        selfpos = max(selfpos, __shfl_xor_sync(~0u, selfpos, o));
    }
    float selfu = u / fmaxf((float)(en - st - 1), 1.f);
    // merged B+C
    float ald = g_ald2[wid];
    float z = 0.f;
    float acc = 0.f;
    for (int base = st; base < en; base += 32) {
        int i = base + lane;
        float p = 0.f;
        int s = 0;
        if (i < en) {
            s = g_csrc[i];
            float ae = (i == selfpos) ? selfu : g_cal2[i];
            p = __expf(lrelu(g_als2[s] + ald + ae));
            g_alpha2[i] = p;          // numerators kept for alpha output pass
            z += p;
        }
        sp[wib][lane] = p;
        ssrc[wib][lane] = s;
        __syncwarp();
        int cnt = min(32, en - base);
        for (int j = 0; j < cnt; j++) {
            int sj = ssrc[wib][j];
            acc += sp[wib][j] * g_h2l[(size_t)sj * 32 + lane];
        }
        __syncwarp();
    }
    #pragma unroll
    for (int o = 16; o; o >>= 1) z += __shfl_xor_sync(~0u, z, o);
    float invz = 1.f / z;
    outH2[wid * 32 + lane] = elu(acc * invz + b2[lane]);
    // pass D: normalized alpha to output (by original edge id)
    if (outAlpha)
        for (int i = st + lane; i < en; i += 32)
            outAlpha[g_ceid[i]] = g_alpha2[i] * invz;
}

// ---------------- edge_index_sl output (as float) ----------------
__global__ void k_eidx(const int* __restrict__ ei, float* __restrict__ out) {
    int t = blockIdx.x * blockDim.x + threadIdx.x;
    if (t >= 2 * EP) return;
    int row = t >= EP;
    int j = t - row * EP;
    int v = (j < EE) ? ei[row * EE + j] : (j - EE);
    out[(size_t)NN * 32 + t] = (float)v;
}

// ---------------- launch ----------------
extern "C" void kernel_launch(void* const* d_in, const int* in_sizes, int n_in,
                              void* d_out, int out_size) {
    int ix, iei, iea, iW1, iW1e, ia1s, ia1d, ia1e, ib1, iW2, iW2e, ia2s, ia2d, ia2e, ib2;
    if (n_in >= 15 && in_sizes[0] == 16384) {
        iW1 = 0; iW1e = 1; iW2 = 2; iW2e = 3;
        ia1d = 4; ia1e = 5; ia1s = 6;
        ia2d = 7; ia2e = 8; ia2s = 9;
        ib1 = 10; ib2 = 11; iea = 12; iei = 13; ix = 14;
    } else {
        ix = 0; iei = 1; iea = 2; iW1 = 3; iW1e = 4;
        ia1s = 5; ia1d = 6; ia1e = 7; ib1 = 8;
        iW2 = 9; iW2e = 10; ia2s = 11; ia2d = 12; ia2e = 13; ib2 = 14;
    }
    const float* x   = (const float*)d_in[ix];
    const int*   ei  = (const int*)d_in[iei];
    const float* ea  = (const float*)d_in[iea];
    const float* W1  = (const float*)d_in[iW1];
    const float* a1s = (const float*)d_in[ia1s];
    const float* a1d = (const float*)d_in[ia1d];
    const float* b1  = (const float*)d_in[ib1];
    const float* W2  = (const float*)d_in[iW2];
    const float* a2s = (const float*)d_in[ia2s];
    const float* a2d = (const float*)d_in[ia2d];
    const float* b2  = (const float*)d_in[ib2];
    const float* W1e = (const float*)d_in[iW1e];
    const float* a1e = (const float*)d_in[ia1e];
    const float* W2e = (const float*)d_in[iW2e];
    const float* a2e = (const float*)d_in[ia2e];
    float* out = (float*)d_out;

    bool full = (out_size >= NN * 32 + 3 * EP);
    float* alphaOut = full ? out + (size_t)NN * 32 + 2 * (size_t)EP : nullptr;

    const int B = 256;
    kz<<<(NN + B - 1) / B, B>>>();
    k_prep<<<1, 128>>>(W1e, a1e, W2e, a2e);
    k_edge<<<EE / 512, 256>>>(ei, ea);                       // 2 edges/thread
    k_scan1<<<NBLK, 1024>>>();
    k_scan2<<<1, 1>>>();
    k_scan3<<<(NN + 1 + B - 1) / B, B>>>();
    k_scatter<<<(EP + B - 1) / B, B>>>(ei);
    k_gemm1t<<<NN / 32, 128>>>(x, W1, a1s, a1d);
    k_agg1f<<<(NN * 32 + B - 1) / B, B>>>(b1);               // warp per node, fused B+C
    k_gemm2t<<<NN / 32, 128>>>(W2, a2s, a2d);
    k_agg2f<<<(NN * 32 + B - 1) / B, B>>>(b2, out, alphaOut);// warp per node, fused B+C
    if (full) k_eidx<<<(2 * EP + B - 1) / B, B>>>(ei, out);
}